// round 1
// baseline (speedup 1.0000x reference)
#include <cuda_runtime.h>
#include <math.h>
#include <stdint.h>

// ---------------- problem constants ----------------
#define S_   2048
#define B_   2
#define H_   1024
#define NH_  16
#define NKV_ 4
#define HD_  64
#define T_   4096            // S_*B_
#define QKV_OUT_ 1536
#define E_   16
#define TOPK_ 2
#define FFN_ 2048
#define CAP_ 640             // ceil(T*K/E*1.25)
#define NSLOT_ (T_*TOPK_)

// ---------------- scratch (device globals; no runtime allocation) ----------------
__device__ float g_ln1[(size_t)T_*H_];
__device__ float g_qkv[(size_t)T_*QKV_OUT_];
__device__ float g_scores[(size_t)B_*NH_*S_*S_];     // 536 MB
__device__ float g_attn[(size_t)T_*H_];
__device__ float g_hattn[(size_t)T_*H_];
__device__ float g_ln2[(size_t)T_*H_];
__device__ int   g_expidx[NSLOT_];
__device__ int   g_pos[NSLOT_];
__device__ float g_gate[NSLOT_];
__device__ float g_buf[(size_t)E_*CAP_*H_];
__device__ float g_h1[(size_t)E_*CAP_*FFN_];
__device__ float g_h2[(size_t)E_*CAP_*H_];

// ---------------- epilogues ----------------
struct EpiStore {
    __device__ __forceinline__ float op(float v, int, int) const { return v; }
};
struct EpiResidual {
    const float* r; int ld;
    __device__ __forceinline__ float op(float v, int m, int n) const {
        return v + r[(size_t)m * ld + n];
    }
};
struct EpiGelu {
    __device__ __forceinline__ float op(float v, int, int) const {
        // JAX default gelu (approximate=True, tanh form)
        float c = 0.7978845608028654f;
        float t = tanhf(c * (v + 0.044715f * v * v * v));
        return 0.5f * v * (1.0f + t);
    }
};

// ---------------- generic 64x64x16 tiled GEMM core (256 threads, 4x4/thread) ----
// C[M,N] = A[M,K] * B^T (BT=true, B is [N,K])  or  A[M,K] * B (BT=false, B is [K,N])
template<bool BT, typename Epi>
__device__ __forceinline__ void gemm_tile(
    const float* __restrict__ A, int lda,
    const float* __restrict__ B, int ldb,
    float* __restrict__ C, int ldc,
    int K, Epi epi)
{
    const int m0 = blockIdx.y * 64;
    const int n0 = blockIdx.x * 64;
    __shared__ float As[16][65];
    __shared__ float Bs[16][65];
    float acc[4][4] = {};
    const int tid = threadIdx.x;
    const int tx = tid & 15;   // n group
    const int ty = tid >> 4;   // m group

    for (int k0 = 0; k0 < K; k0 += 16) {
        #pragma unroll
        for (int r = 0; r < 4; r++) {
            int i = tid + r * 256;
            int m = i >> 4, k = i & 15;
            As[k][m] = A[(size_t)(m0 + m) * lda + (k0 + k)];
        }
        if (BT) {
            #pragma unroll
            for (int r = 0; r < 4; r++) {
                int i = tid + r * 256;
                int n = i >> 4, k = i & 15;
                Bs[k][n] = B[(size_t)(n0 + n) * ldb + (k0 + k)];
            }
        } else {
            #pragma unroll
            for (int r = 0; r < 4; r++) {
                int i = tid + r * 256;
                int k = i >> 6, n = i & 63;
                Bs[k][n] = B[(size_t)(k0 + k) * ldb + (n0 + n)];
            }
        }
        __syncthreads();
        #pragma unroll
        for (int k = 0; k < 16; k++) {
            float a[4], b[4];
            #pragma unroll
            for (int i = 0; i < 4; i++) a[i] = As[k][ty * 4 + i];
            #pragma unroll
            for (int j = 0; j < 4; j++) b[j] = Bs[k][tx * 4 + j];
            #pragma unroll
            for (int i = 0; i < 4; i++)
                #pragma unroll
                for (int j = 0; j < 4; j++)
                    acc[i][j] = fmaf(a[i], b[j], acc[i][j]);
        }
        __syncthreads();
    }
    #pragma unroll
    for (int i = 0; i < 4; i++) {
        int gm = m0 + ty * 4 + i;
        #pragma unroll
        for (int j = 0; j < 4; j++) {
            int gn = n0 + tx * 4 + j;
            C[(size_t)gm * ldc + gn] = epi.op(acc[i][j], gm, gn);
        }
    }
}

// ---------------- GEMM wrappers ----------------
template<typename Epi>
__global__ void k_gemm_nt(const float* __restrict__ A, int lda,
                          const float* __restrict__ B, int ldb,
                          float* __restrict__ C, int ldc, int K, Epi epi)
{
    gemm_tile<true>(A, lda, B, ldb, C, ldc, K, epi);
}

// scores[bh, q, k] = sum_d Q[q] * K[k];  skip tiles entirely above the diagonal
__global__ void k_scores(const float* __restrict__ qkv, float* __restrict__ scores)
{
    if (blockIdx.x > blockIdx.y) return;   // fully masked tile
    int bh = blockIdx.z;
    int b = bh >> 4, hq = bh & 15, hk = hq >> 2;
    const float* Aq = qkv + (size_t)b * QKV_OUT_ + hq * HD_;
    const float* Bk = qkv + (size_t)b * QKV_OUT_ + NH_ * HD_ + hk * HD_;
    float* C = scores + (size_t)bh * S_ * S_;
    gemm_tile<true>(Aq, B_ * QKV_OUT_, Bk, B_ * QKV_OUT_, C, S_, HD_, EpiStore{});
}

// attn_out[q, b, hq*64+d] = sum_{k<=q} P[q,k] * V[k,d]; K clipped to causal extent
__global__ void k_pv(const float* __restrict__ scores, const float* __restrict__ qkv,
                     float* __restrict__ attn)
{
    int bh = blockIdx.z;
    int b = bh >> 4, hq = bh & 15, hk = hq >> 2;
    const float* A = scores + (size_t)bh * S_ * S_;
    const float* Bv = qkv + (size_t)b * QKV_OUT_ + (NH_ + NKV_) * HD_ + hk * HD_;
    float* C = attn + (size_t)b * H_ + hq * HD_;
    int Keff = (blockIdx.y + 1) * 64;      // rows > q are zero after softmax; skip them
    gemm_tile<false>(A, S_, Bv, B_ * QKV_OUT_, C, B_ * H_, Keff, EpiStore{});
}

__global__ void k_fc1(const float* __restrict__ buf, const float* __restrict__ w1,
                      float* __restrict__ h1)
{
    int e = blockIdx.z;
    gemm_tile<true>(buf + (size_t)e * CAP_ * H_, H_,
                    w1 + (size_t)e * FFN_ * H_, H_,
                    h1 + (size_t)e * CAP_ * FFN_, FFN_, H_, EpiGelu{});
}

__global__ void k_fc2(const float* __restrict__ h1, const float* __restrict__ w2,
                      float* __restrict__ h2)
{
    int e = blockIdx.z;
    gemm_tile<true>(h1 + (size_t)e * CAP_ * FFN_, FFN_,
                    w2 + (size_t)e * H_ * FFN_, FFN_,
                    h2 + (size_t)e * CAP_ * H_, H_, FFN_, EpiStore{});
}

// ---------------- layernorm ----------------
__global__ void k_layernorm(const float* __restrict__ x, const float* __restrict__ w,
                            const float* __restrict__ b, float* __restrict__ y)
{
    int t = blockIdx.x;
    const float* xr = x + (size_t)t * H_;
    float* yr = y + (size_t)t * H_;
    float v[4], s = 0.f, s2 = 0.f;
    #pragma unroll
    for (int i = 0; i < 4; i++) {
        v[i] = xr[threadIdx.x + i * 256];
        s += v[i]; s2 += v[i] * v[i];
    }
    __shared__ float r1[256], r2[256];
    r1[threadIdx.x] = s; r2[threadIdx.x] = s2;
    __syncthreads();
    for (int o = 128; o; o >>= 1) {
        if (threadIdx.x < o) {
            r1[threadIdx.x] += r1[threadIdx.x + o];
            r2[threadIdx.x] += r2[threadIdx.x + o];
        }
        __syncthreads();
    }
    float mean = r1[0] * (1.0f / H_);
    float var  = r2[0] * (1.0f / H_) - mean * mean;
    float inv  = rsqrtf(var + 1e-5f);
    #pragma unroll
    for (int i = 0; i < 4; i++) {
        int h = threadIdx.x + i * 256;
        yr[h] = (v[i] - mean) * inv * w[h] + b[h];
    }
}

// ---------------- causal row softmax (scale folded in) ----------------
__global__ void k_softmax(float* __restrict__ scores)
{
    int q = blockIdx.x, bh = blockIdx.y;
    float* row = scores + ((size_t)bh * S_ + q) * S_;
    const int n = q + 1;
    const float scale = 0.125f;   // 1/sqrt(64)
    __shared__ float red[256];

    float m = -1e30f;
    for (int k = threadIdx.x; k < n; k += 256) m = fmaxf(m, row[k]);
    red[threadIdx.x] = m; __syncthreads();
    for (int o = 128; o; o >>= 1) {
        if (threadIdx.x < o) red[threadIdx.x] = fmaxf(red[threadIdx.x], red[threadIdx.x + o]);
        __syncthreads();
    }
    float rmax = red[0] * scale;
    __syncthreads();

    float s = 0.f;
    for (int k = threadIdx.x; k < n; k += 256) {
        float e = expf(row[k] * scale - rmax);
        row[k] = e; s += e;
    }
    red[threadIdx.x] = s; __syncthreads();
    for (int o = 128; o; o >>= 1) {
        if (threadIdx.x < o) red[threadIdx.x] += red[threadIdx.x + o];
        __syncthreads();
    }
    float inv = 1.0f / red[0];

    for (int k = threadIdx.x; k < n; k += 256) row[k] *= inv;
    for (int k = n + threadIdx.x; k < S_; k += 256) row[k] = 0.f;  // PV reads these
}

// ---------------- router: logits -> softmax -> top-2 ----------------
__global__ void k_router(const float* __restrict__ ln2, const float* __restrict__ Wr,
                         int* __restrict__ expidx, float* __restrict__ gate)
{
    int t = blockIdx.x;
    __shared__ float logits[E_];
    int w = threadIdx.x >> 5, lane = threadIdx.x & 31;   // 16 warps, one per expert
    const float* x = ln2 + (size_t)t * H_;
    const float* wr = Wr + (size_t)w * H_;
    float s = 0.f;
    for (int i = lane; i < H_; i += 32) s += x[i] * wr[i];
    #pragma unroll
    for (int o = 16; o; o >>= 1) s += __shfl_xor_sync(0xFFFFFFFFu, s, o);
    if (lane == 0) logits[w] = s;
    __syncthreads();
    if (threadIdx.x == 0) {
        float lmax = -1e30f;
        #pragma unroll
        for (int e = 0; e < E_; e++) lmax = fmaxf(lmax, logits[e]);
        float den = 0.f;
        #pragma unroll
        for (int e = 0; e < E_; e++) den += expf(logits[e] - lmax);
        int i1 = 0; float v1 = logits[0];
        #pragma unroll
        for (int e = 1; e < E_; e++) if (logits[e] > v1) { v1 = logits[e]; i1 = e; }
        int i2 = -1; float v2 = -1e30f;
        #pragma unroll
        for (int e = 0; e < E_; e++) if (e != i1 && logits[e] > v2) { v2 = logits[e]; i2 = e; }
        float inv = 1.0f / den;
        expidx[2 * t]     = i1;  gate[2 * t]     = expf(v1 - lmax) * inv;
        expidx[2 * t + 1] = i2;  gate[2 * t + 1] = expf(v2 - lmax) * inv;
    }
}

// ---------------- slot positions: cumulative count per expert in slot order ----
__global__ void k_pos(const int* __restrict__ expidx, int* __restrict__ pos)
{
    __shared__ int sidx[NSLOT_];  // 32 KB
    for (int i = threadIdx.x; i < NSLOT_; i += blockDim.x) sidx[i] = expidx[i];
    __syncthreads();
    if (threadIdx.x < E_) {
        int e = threadIdx.x, c = 0;
        for (int j = 0; j < NSLOT_; j++)
            if (sidx[j] == e) pos[j] = c++;
    }
}

// ---------------- zero expert buffer ----------------
__global__ void k_zero(float* __restrict__ p)
{
    float4 z = make_float4(0.f, 0.f, 0.f, 0.f);
    ((float4*)p)[(size_t)blockIdx.x * 1024 + threadIdx.x] = z;
}

// ---------------- dispatch kept slots into expert buffer ----------------
__global__ void k_dispatch(const float* __restrict__ ln2, const int* __restrict__ expidx,
                           const int* __restrict__ pos, float* __restrict__ buf)
{
    int slot = blockIdx.x;
    int p = pos[slot];
    if (p >= CAP_) return;
    int e = expidx[slot];
    int t = slot >> 1;
    const float* src = ln2 + (size_t)t * H_;
    float* dst = buf + ((size_t)e * CAP_ + p) * H_;
    for (int h = threadIdx.x; h < H_; h += 256) dst[h] = src[h];
}

// ---------------- combine: residual + gated expert outputs ----------------
__global__ void k_combine(const float* __restrict__ hattn, const float* __restrict__ h2,
                          const int* __restrict__ expidx, const int* __restrict__ pos,
                          const float* __restrict__ gate, float* __restrict__ out)
{
    int t = blockIdx.x;
    int s0 = 2 * t, s1 = 2 * t + 1;
    int p0 = pos[s0], p1 = pos[s1];
    int e0 = expidx[s0], e1 = expidx[s1];
    float g0 = (p0 < CAP_) ? gate[s0] : 0.f;
    float g1 = (p1 < CAP_) ? gate[s1] : 0.f;
    const float* r0 = (p0 < CAP_) ? h2 + ((size_t)e0 * CAP_ + p0) * H_ : nullptr;
    const float* r1 = (p1 < CAP_) ? h2 + ((size_t)e1 * CAP_ + p1) * H_ : nullptr;
    for (int h = threadIdx.x; h < H_; h += 256) {
        float v = hattn[(size_t)t * H_ + h];
        if (r0) v += r0[h] * g0;
        if (r1) v += r1[h] * g1;
        out[(size_t)t * H_ + h] = v;
    }
}

// ---------------- launch ----------------
extern "C" void kernel_launch(void* const* d_in, const int* in_sizes, int n_in,
                              void* d_out, int out_size)
{
    const float* hidden  = (const float*)d_in[0];
    const float* ln1w    = (const float*)d_in[1];
    const float* ln1b    = (const float*)d_in[2];
    const float* ln2w    = (const float*)d_in[3];
    const float* ln2b    = (const float*)d_in[4];
    const float* qkvw    = (const float*)d_in[5];
    const float* projw   = (const float*)d_in[6];
    const float* routerw = (const float*)d_in[7];
    const float* w1      = (const float*)d_in[8];
    const float* w2      = (const float*)d_in[9];
    float* out = (float*)d_out;

    float *ln1, *qkv, *scores, *attn, *hattn, *ln2, *gatep, *buf, *h1, *h2;
    int *expidx, *pos;
    cudaGetSymbolAddress((void**)&ln1,    g_ln1);
    cudaGetSymbolAddress((void**)&qkv,    g_qkv);
    cudaGetSymbolAddress((void**)&scores, g_scores);
    cudaGetSymbolAddress((void**)&attn,   g_attn);
    cudaGetSymbolAddress((void**)&hattn,  g_hattn);
    cudaGetSymbolAddress((void**)&ln2,    g_ln2);
    cudaGetSymbolAddress((void**)&expidx, g_expidx);
    cudaGetSymbolAddress((void**)&pos,    g_pos);
    cudaGetSymbolAddress((void**)&gatep,  g_gate);
    cudaGetSymbolAddress((void**)&buf,    g_buf);
    cudaGetSymbolAddress((void**)&h1,     g_h1);
    cudaGetSymbolAddress((void**)&h2,     g_h2);

    // LN1
    k_layernorm<<<T_, 256>>>(hidden, ln1w, ln1b, ln1);
    // QKV = ln1 @ W_qkv^T   [4096,1024]x[1536,1024]^T
    k_gemm_nt<<<dim3(QKV_OUT_ / 64, T_ / 64), 256>>>(ln1, H_, qkvw, H_, qkv, QKV_OUT_, H_, EpiStore{});
    // scores = Q K^T (causal tiles only)
    k_scores<<<dim3(S_ / 64, S_ / 64, B_ * NH_), 256>>>(qkv, scores);
    // causal softmax rows
    k_softmax<<<dim3(S_, B_ * NH_), 256>>>(scores);
    // attn = P V
    k_pv<<<dim3(1, S_ / 64, B_ * NH_), 256>>>(scores, qkv, attn);
    // proj + residual
    k_gemm_nt<<<dim3(H_ / 64, T_ / 64), 256>>>(attn, H_, projw, H_, hattn, H_, H_, EpiResidual{hidden, H_});
    // LN2
    k_layernorm<<<T_, 256>>>(hattn, ln2w, ln2b, ln2);
    // router top-2
    k_router<<<T_, 512>>>(ln2, routerw, expidx, gatep);
    // slot positions (cumsum per expert, slot order)
    k_pos<<<1, 256>>>(expidx, pos);
    // zero + dispatch expert buffer
    k_zero<<<(E_ * CAP_ * H_) / 4096, 1024>>>(buf);
    k_dispatch<<<NSLOT_, 256>>>(ln2, expidx, pos, buf);
    // expert FC1 (gelu) and FC2
    k_fc1<<<dim3(FFN_ / 64, CAP_ / 64, E_), 256>>>(buf, w1, h1);
    k_fc2<<<dim3(H_ / 64, CAP_ / 64, E_), 256>>>(h1, w2, h2);
    // combine + final residual
    k_combine<<<T_, 256>>>(hattn, h2, expidx, pos, gatep, out);
}

// round 3
// speedup vs baseline: 2.1345x; 2.1345x over previous
#include <cuda_runtime.h>
#include <cuda_bf16.h>
#include <math.h>
#include <stdint.h>

// ---------------- problem constants ----------------
#define S_   2048
#define B_   2
#define H_   1024
#define NH_  16
#define NKV_ 4
#define HD_  64
#define T_   4096            // S_*B_
#define QKV_OUT_ 1536
#define E_   16
#define TOPK_ 2
#define FFN_ 2048
#define CAP_ 640             // ceil(T*K/E*1.25)
#define NSLOT_ (T_*TOPK_)

// ---------------- scratch (device globals; no runtime allocation) ----------------
__device__ float g_ln1[(size_t)T_*H_];
__device__ float g_qkv[(size_t)T_*QKV_OUT_];
__device__ float g_scores[(size_t)B_*NH_*S_*S_];     // 536 MB
__device__ float g_attn[(size_t)T_*H_];
__device__ float g_hattn[(size_t)T_*H_];
__device__ float g_ln2[(size_t)T_*H_];
__device__ int   g_expidx[NSLOT_];
__device__ int   g_pos[NSLOT_];
__device__ float g_gate[NSLOT_];
__device__ float g_buf[(size_t)E_*CAP_*H_];
__device__ float g_h1[(size_t)E_*CAP_*FFN_];
__device__ float g_h2[(size_t)E_*CAP_*H_];

// =====================================================================
// PTX helpers (baseline sm_80+ ISA only — tcgen05 is NOT available on
// this build target, verified by R2 ptxas errors)
// =====================================================================
__device__ __forceinline__ uint32_t smem_to_u32(const void* smem_ptr) {
    uint32_t addr;
    asm("{ .reg .u64 tmp; cvta.to.shared.u64 tmp, %1; cvt.u32.u64 %0, tmp; }"
        : "=r"(addr) : "l"(smem_ptr));
    return addr;
}

#define CVT_BF16X2_F32(result, a, b) \
    asm("cvt.rn.satfinite.bf16x2.f32 %0, %1, %2;" : "=r"(result) : "f"(b), "f"(a))

__device__ __forceinline__ void ldsm_x4(uint32_t& r0, uint32_t& r1,
                                        uint32_t& r2, uint32_t& r3, uint32_t addr) {
    asm volatile("ldmatrix.sync.aligned.m8n8.x4.shared.b16 {%0,%1,%2,%3}, [%4];"
                 : "=r"(r0), "=r"(r1), "=r"(r2), "=r"(r3) : "r"(addr));
}

__device__ __forceinline__ void mma16816(float* c,
        uint32_t a0, uint32_t a1, uint32_t a2, uint32_t a3,
        uint32_t b0, uint32_t b1) {
    asm volatile(
        "mma.sync.aligned.m16n8k16.row.col.f32.bf16.bf16.f32 "
        "{%0,%1,%2,%3}, {%4,%5,%6,%7}, {%8,%9}, {%0,%1,%2,%3};"
        : "+f"(c[0]), "+f"(c[1]), "+f"(c[2]), "+f"(c[3])
        : "r"(a0), "r"(a1), "r"(a2), "r"(a3), "r"(b0), "r"(b1));
}

// ---------------- epilogues ----------------
struct EpiStore {
    __device__ __forceinline__ float op(float v, int, int) const { return v; }
};
struct EpiResidual {
    const float* r; int ld;
    __device__ __forceinline__ float op(float v, int m, int n) const {
        return v + r[(size_t)m * ld + n];
    }
};
struct EpiGelu {
    __device__ __forceinline__ float op(float v, int, int) const {
        float c = 0.7978845608028654f;
        float t = tanhf(c * (v + 0.044715f * v * v * v));
        return 0.5f * v * (1.0f + t);
    }
};

// =====================================================================
// split-bf16 HMMA NT GEMM: C[M,N] = A[M,K] * B[N,K]^T (fp32 in/out)
// 128x128 block tile, 8 warps (64x32 each), K-chunk 64 fp32.
// SMEM holds [hi(64) | lo(64)] bf16 per row; 12 k16-steps per chunk
// select offset pairs implementing  Ahi*Bhi + Alo*Bhi + Ahi*Blo.
// rel err ~1e-5, well under the 1e-3 gate.
// =====================================================================
#define CH_  64
#define AST  136                      // smem row stride (bf16 elems)
#define HMMA_SMEM_BYTES (2 * 128 * AST * 2)   // 69632

template<typename Epi>
__global__ void __launch_bounds__(256, 2)
k_hmma_nt(const float* __restrict__ A, int lda, size_t aB,
          const float* __restrict__ B, int ldb, size_t bB,
          float* __restrict__ C, int ldc, size_t cB,
          int K, Epi epi)
{
    extern __shared__ __nv_bfloat16 sm[];
    __nv_bfloat16 (*As)[AST] = (__nv_bfloat16(*)[AST])sm;
    __nv_bfloat16 (*Bs)[AST] = (__nv_bfloat16(*)[AST])(sm + 128 * AST);

    const int tid = threadIdx.x, lane = tid & 31, wid = tid >> 5;
    const int m0 = blockIdx.y * 128, n0 = blockIdx.x * 128;
    A += (size_t)blockIdx.z * aB;
    B += (size_t)blockIdx.z * bB;
    C += (size_t)blockIdx.z * cB;
    const int warpM = (wid >> 2) * 64, warpN = (wid & 3) * 32;

    float acc[4][4][4] = {};

    const uint32_t sA = smem_to_u32(As), sB = smem_to_u32(Bs);
    const int lrow = lane & 15, lsel = lane >> 4;

    for (int k0 = 0; k0 < K; k0 += CH_) {
        // ---- load fp32, split into (hi, lo) bf16, store to SMEM ----
        #pragma unroll
        for (int i = 0; i < 8; i++) {
            int f = tid + i * 256;           // 0..2047 float4 slots
            int row = f >> 4;                // 128 rows
            int kq = f & 15;                 // 16 float4 per row (64 floats)

            float4 va = *(const float4*)&A[(size_t)(m0 + row) * lda + k0 + kq * 4];
            uint32_t h01, h23, l01, l23;
            CVT_BF16X2_F32(h01, va.x, va.y);
            CVT_BF16X2_F32(h23, va.z, va.w);
            float f0 = __uint_as_float(h01 << 16), f1 = __uint_as_float(h01 & 0xFFFF0000u);
            float f2 = __uint_as_float(h23 << 16), f3 = __uint_as_float(h23 & 0xFFFF0000u);
            CVT_BF16X2_F32(l01, va.x - f0, va.y - f1);
            CVT_BF16X2_F32(l23, va.z - f2, va.w - f3);
            *(uint2*)&As[row][kq * 4]      = make_uint2(h01, h23);
            *(uint2*)&As[row][64 + kq * 4] = make_uint2(l01, l23);

            float4 vb = *(const float4*)&B[(size_t)(n0 + row) * ldb + k0 + kq * 4];
            CVT_BF16X2_F32(h01, vb.x, vb.y);
            CVT_BF16X2_F32(h23, vb.z, vb.w);
            f0 = __uint_as_float(h01 << 16); f1 = __uint_as_float(h01 & 0xFFFF0000u);
            f2 = __uint_as_float(h23 << 16); f3 = __uint_as_float(h23 & 0xFFFF0000u);
            CVT_BF16X2_F32(l01, vb.x - f0, vb.y - f1);
            CVT_BF16X2_F32(l23, vb.z - f2, vb.w - f3);
            *(uint2*)&Bs[row][kq * 4]      = make_uint2(h01, h23);
            *(uint2*)&Bs[row][64 + kq * 4] = make_uint2(l01, l23);
        }
        __syncthreads();

        // ---- 12 k16-steps: hi*hi (4), lo*hi (4), hi*lo (4) ----
        const int AO[12] = {0,16,32,48, 64,80,96,112, 0,16,32,48};
        const int BO[12] = {0,16,32,48, 0,16,32,48, 64,80,96,112};
        #pragma unroll
        for (int s = 0; s < 12; s++) {
            uint32_t af[4][4];
            #pragma unroll
            for (int mt = 0; mt < 4; mt++) {
                uint32_t addr = sA +
                    ((uint32_t)(warpM + mt * 16 + lrow) * AST + AO[s] + lsel * 8) * 2;
                ldsm_x4(af[mt][0], af[mt][1], af[mt][2], af[mt][3], addr);
            }
            uint32_t bf[4][2];
            #pragma unroll
            for (int pt = 0; pt < 2; pt++) {
                uint32_t r0, r1, r2, r3;
                uint32_t addr = sB +
                    ((uint32_t)(warpN + pt * 16 + lrow) * AST + BO[s] + lsel * 8) * 2;
                ldsm_x4(r0, r1, r2, r3, addr);
                bf[pt * 2][0] = r0;     bf[pt * 2][1] = r2;
                bf[pt * 2 + 1][0] = r1; bf[pt * 2 + 1][1] = r3;
            }
            #pragma unroll
            for (int mt = 0; mt < 4; mt++)
                #pragma unroll
                for (int nt = 0; nt < 4; nt++)
                    mma16816(acc[mt][nt], af[mt][0], af[mt][1], af[mt][2], af[mt][3],
                             bf[nt][0], bf[nt][1]);
        }
        __syncthreads();
    }

    // ---- epilogue: direct register -> global ----
    const int r = lane >> 2, cpair = (lane & 3) * 2;
    #pragma unroll
    for (int mt = 0; mt < 4; mt++) {
        int gm0 = m0 + warpM + mt * 16 + r;
        #pragma unroll
        for (int nt = 0; nt < 4; nt++) {
            int gn = n0 + warpN + nt * 8 + cpair;
            float2 v0 = make_float2(epi.op(acc[mt][nt][0], gm0, gn),
                                    epi.op(acc[mt][nt][1], gm0, gn + 1));
            *(float2*)&C[(size_t)gm0 * ldc + gn] = v0;
            float2 v1 = make_float2(epi.op(acc[mt][nt][2], gm0 + 8, gn),
                                    epi.op(acc[mt][nt][3], gm0 + 8, gn + 1));
            *(float2*)&C[(size_t)(gm0 + 8) * ldc + gn] = v1;
        }
    }
}

// =====================================================================
// SIMT 64x64 GEMM (attention scores / PV)
// =====================================================================
template<bool BT, typename Epi>
__device__ __forceinline__ void gemm_tile(
    const float* __restrict__ A, int lda,
    const float* __restrict__ B, int ldb,
    float* __restrict__ C, int ldc,
    int K, Epi epi)
{
    const int m0 = blockIdx.y * 64;
    const int n0 = blockIdx.x * 64;
    __shared__ float As[16][65];
    __shared__ float Bs[16][65];
    float acc[4][4] = {};
    const int tid = threadIdx.x;
    const int tx = tid & 15;
    const int ty = tid >> 4;

    for (int k0 = 0; k0 < K; k0 += 16) {
        #pragma unroll
        for (int r = 0; r < 4; r++) {
            int i = tid + r * 256;
            int m = i >> 4, k = i & 15;
            As[k][m] = A[(size_t)(m0 + m) * lda + (k0 + k)];
        }
        if (BT) {
            #pragma unroll
            for (int r = 0; r < 4; r++) {
                int i = tid + r * 256;
                int n = i >> 4, k = i & 15;
                Bs[k][n] = B[(size_t)(n0 + n) * ldb + (k0 + k)];
            }
        } else {
            #pragma unroll
            for (int r = 0; r < 4; r++) {
                int i = tid + r * 256;
                int k = i >> 6, n = i & 63;
                Bs[k][n] = B[(size_t)(k0 + k) * ldb + (n0 + n)];
            }
        }
        __syncthreads();
        #pragma unroll
        for (int k = 0; k < 16; k++) {
            float a[4], b[4];
            #pragma unroll
            for (int i = 0; i < 4; i++) a[i] = As[k][ty * 4 + i];
            #pragma unroll
            for (int j = 0; j < 4; j++) b[j] = Bs[k][tx * 4 + j];
            #pragma unroll
            for (int i = 0; i < 4; i++)
                #pragma unroll
                for (int j = 0; j < 4; j++)
                    acc[i][j] = fmaf(a[i], b[j], acc[i][j]);
        }
        __syncthreads();
    }
    #pragma unroll
    for (int i = 0; i < 4; i++) {
        int gm = m0 + ty * 4 + i;
        #pragma unroll
        for (int j = 0; j < 4; j++) {
            int gn = n0 + tx * 4 + j;
            C[(size_t)gm * ldc + gn] = epi.op(acc[i][j], gm, gn);
        }
    }
}

// scores[bh, q, k] = Q·K^T, causal tiles only
__global__ void k_scores(const float* __restrict__ qkv, float* __restrict__ scores)
{
    if (blockIdx.x > blockIdx.y) return;
    int bh = blockIdx.z;
    int b = bh >> 4, hq = bh & 15, hk = hq >> 2;
    const float* Aq = qkv + (size_t)b * QKV_OUT_ + hq * HD_;
    const float* Bk = qkv + (size_t)b * QKV_OUT_ + NH_ * HD_ + hk * HD_;
    float* C = scores + (size_t)bh * S_ * S_;
    gemm_tile<true>(Aq, B_ * QKV_OUT_, Bk, B_ * QKV_OUT_, C, S_, HD_, EpiStore{});
}

// attn = P·V with K clipped to causal extent
__global__ void k_pv(const float* __restrict__ scores, const float* __restrict__ qkv,
                     float* __restrict__ attn)
{
    int bh = blockIdx.z;
    int b = bh >> 4, hq = bh & 15, hk = hq >> 2;
    const float* A = scores + (size_t)bh * S_ * S_;
    const float* Bv = qkv + (size_t)b * QKV_OUT_ + (NH_ + NKV_) * HD_ + hk * HD_;
    float* C = attn + (size_t)b * H_ + hq * HD_;
    int Keff = (blockIdx.y + 1) * 64;
    gemm_tile<false>(A, S_, Bv, B_ * QKV_OUT_, C, B_ * H_, Keff, EpiStore{});
}

// ---------------- layernorm ----------------
__global__ void k_layernorm(const float* __restrict__ x, const float* __restrict__ w,
                            const float* __restrict__ b, float* __restrict__ y)
{
    int t = blockIdx.x;
    const float* xr = x + (size_t)t * H_;
    float* yr = y + (size_t)t * H_;
    float v[4], s = 0.f, s2 = 0.f;
    #pragma unroll
    for (int i = 0; i < 4; i++) {
        v[i] = xr[threadIdx.x + i * 256];
        s += v[i]; s2 += v[i] * v[i];
    }
    __shared__ float r1[256], r2[256];
    r1[threadIdx.x] = s; r2[threadIdx.x] = s2;
    __syncthreads();
    for (int o = 128; o; o >>= 1) {
        if (threadIdx.x < o) {
            r1[threadIdx.x] += r1[threadIdx.x + o];
            r2[threadIdx.x] += r2[threadIdx.x + o];
        }
        __syncthreads();
    }
    float mean = r1[0] * (1.0f / H_);
    float var  = r2[0] * (1.0f / H_) - mean * mean;
    float inv  = rsqrtf(var + 1e-5f);
    #pragma unroll
    for (int i = 0; i < 4; i++) {
        int h = threadIdx.x + i * 256;
        yr[h] = (v[i] - mean) * inv * w[h] + b[h];
    }
}

// ---------------- causal row softmax ----------------
__global__ void k_softmax(float* __restrict__ scores)
{
    int q = blockIdx.x, bh = blockIdx.y;
    float* row = scores + ((size_t)bh * S_ + q) * S_;
    const int n = q + 1;
    const float scale = 0.125f;
    __shared__ float red[256];

    float m = -1e30f;
    for (int k = threadIdx.x; k < n; k += 256) m = fmaxf(m, row[k]);
    red[threadIdx.x] = m; __syncthreads();
    for (int o = 128; o; o >>= 1) {
        if (threadIdx.x < o) red[threadIdx.x] = fmaxf(red[threadIdx.x], red[threadIdx.x + o]);
        __syncthreads();
    }
    float rmax = red[0] * scale;
    __syncthreads();

    float s = 0.f;
    for (int k = threadIdx.x; k < n; k += 256) {
        float e = expf(row[k] * scale - rmax);
        row[k] = e; s += e;
    }
    red[threadIdx.x] = s; __syncthreads();
    for (int o = 128; o; o >>= 1) {
        if (threadIdx.x < o) red[threadIdx.x] += red[threadIdx.x + o];
        __syncthreads();
    }
    float inv = 1.0f / red[0];

    for (int k = threadIdx.x; k < n; k += 256) row[k] *= inv;
    for (int k = n + threadIdx.x; k < S_; k += 256) row[k] = 0.f;
}

// ---------------- router ----------------
__global__ void k_router(const float* __restrict__ ln2, const float* __restrict__ Wr,
                         int* __restrict__ expidx, float* __restrict__ gate)
{
    int t = blockIdx.x;
    __shared__ float logits[E_];
    int w = threadIdx.x >> 5, lane = threadIdx.x & 31;
    const float* x = ln2 + (size_t)t * H_;
    const float* wr = Wr + (size_t)w * H_;
    float s = 0.f;
    for (int i = lane; i < H_; i += 32) s += x[i] * wr[i];
    #pragma unroll
    for (int o = 16; o; o >>= 1) s += __shfl_xor_sync(0xFFFFFFFFu, s, o);
    if (lane == 0) logits[w] = s;
    __syncthreads();
    if (threadIdx.x == 0) {
        float lmax = -1e30f;
        #pragma unroll
        for (int e = 0; e < E_; e++) lmax = fmaxf(lmax, logits[e]);
        float den = 0.f;
        #pragma unroll
        for (int e = 0; e < E_; e++) den += expf(logits[e] - lmax);
        int i1 = 0; float v1 = logits[0];
        #pragma unroll
        for (int e = 1; e < E_; e++) if (logits[e] > v1) { v1 = logits[e]; i1 = e; }
        int i2 = -1; float v2 = -1e30f;
        #pragma unroll
        for (int e = 0; e < E_; e++) if (e != i1 && logits[e] > v2) { v2 = logits[e]; i2 = e; }
        float inv = 1.0f / den;
        expidx[2 * t]     = i1;  gate[2 * t]     = expf(v1 - lmax) * inv;
        expidx[2 * t + 1] = i2;  gate[2 * t + 1] = expf(v2 - lmax) * inv;
    }
}

// ---------------- slot positions ----------------
__global__ void k_pos(const int* __restrict__ expidx, int* __restrict__ pos)
{
    __shared__ int sidx[NSLOT_];
    for (int i = threadIdx.x; i < NSLOT_; i += blockDim.x) sidx[i] = expidx[i];
    __syncthreads();
    if (threadIdx.x < E_) {
        int e = threadIdx.x, c = 0;
        for (int j = 0; j < NSLOT_; j++)
            if (sidx[j] == e) pos[j] = c++;
    }
}

__global__ void k_zero(float* __restrict__ p)
{
    float4 z = make_float4(0.f, 0.f, 0.f, 0.f);
    ((float4*)p)[(size_t)blockIdx.x * 1024 + threadIdx.x] = z;
}

__global__ void k_dispatch(const float* __restrict__ ln2, const int* __restrict__ expidx,
                           const int* __restrict__ pos, float* __restrict__ buf)
{
    int slot = blockIdx.x;
    int p = pos[slot];
    if (p >= CAP_) return;
    int e = expidx[slot];
    int t = slot >> 1;
    const float* src = ln2 + (size_t)t * H_;
    float* dst = buf + ((size_t)e * CAP_ + p) * H_;
    for (int h = threadIdx.x; h < H_; h += 256) dst[h] = src[h];
}

__global__ void k_combine(const float* __restrict__ hattn, const float* __restrict__ h2,
                          const int* __restrict__ expidx, const int* __restrict__ pos,
                          const float* __restrict__ gate, float* __restrict__ out)
{
    int t = blockIdx.x;
    int s0 = 2 * t, s1 = 2 * t + 1;
    int p0 = pos[s0], p1 = pos[s1];
    int e0 = expidx[s0], e1 = expidx[s1];
    float g0 = (p0 < CAP_) ? gate[s0] : 0.f;
    float g1 = (p1 < CAP_) ? gate[s1] : 0.f;
    const float* r0 = (p0 < CAP_) ? h2 + ((size_t)e0 * CAP_ + p0) * H_ : nullptr;
    const float* r1 = (p1 < CAP_) ? h2 + ((size_t)e1 * CAP_ + p1) * H_ : nullptr;
    for (int h = threadIdx.x; h < H_; h += 256) {
        float v = hattn[(size_t)t * H_ + h];
        if (r0) v += r0[h] * g0;
        if (r1) v += r1[h] * g1;
        out[(size_t)t * H_ + h] = v;
    }
}

// ---------------- launch ----------------
extern "C" void kernel_launch(void* const* d_in, const int* in_sizes, int n_in,
                              void* d_out, int out_size)
{
    const float* hidden  = (const float*)d_in[0];
    const float* ln1w    = (const float*)d_in[1];
    const float* ln1b    = (const float*)d_in[2];
    const float* ln2w    = (const float*)d_in[3];
    const float* ln2b    = (const float*)d_in[4];
    const float* qkvw    = (const float*)d_in[5];
    const float* projw   = (const float*)d_in[6];
    const float* routerw = (const float*)d_in[7];
    const float* w1      = (const float*)d_in[8];
    const float* w2      = (const float*)d_in[9];
    float* out = (float*)d_out;

    float *ln1, *qkv, *scores, *attn, *hattn, *ln2, *gatep, *buf, *h1, *h2;
    int *expidx, *pos;
    cudaGetSymbolAddress((void**)&ln1,    g_ln1);
    cudaGetSymbolAddress((void**)&qkv,    g_qkv);
    cudaGetSymbolAddress((void**)&scores, g_scores);
    cudaGetSymbolAddress((void**)&attn,   g_attn);
    cudaGetSymbolAddress((void**)&hattn,  g_hattn);
    cudaGetSymbolAddress((void**)&ln2,    g_ln2);
    cudaGetSymbolAddress((void**)&expidx, g_expidx);
    cudaGetSymbolAddress((void**)&pos,    g_pos);
    cudaGetSymbolAddress((void**)&gatep,  g_gate);
    cudaGetSymbolAddress((void**)&buf,    g_buf);
    cudaGetSymbolAddress((void**)&h1,     g_h1);
    cudaGetSymbolAddress((void**)&h2,     g_h2);

    cudaFuncSetAttribute((void*)k_hmma_nt<EpiStore>,
                         cudaFuncAttributeMaxDynamicSharedMemorySize, HMMA_SMEM_BYTES);
    cudaFuncSetAttribute((void*)k_hmma_nt<EpiResidual>,
                         cudaFuncAttributeMaxDynamicSharedMemorySize, HMMA_SMEM_BYTES);
    cudaFuncSetAttribute((void*)k_hmma_nt<EpiGelu>,
                         cudaFuncAttributeMaxDynamicSharedMemorySize, HMMA_SMEM_BYTES);

    // LN1
    k_layernorm<<<T_, 256>>>(hidden, ln1w, ln1b, ln1);
    // QKV = ln1 @ W_qkv^T (HMMA split-bf16)
    k_hmma_nt<<<dim3(QKV_OUT_ / 128, T_ / 128, 1), 256, HMMA_SMEM_BYTES>>>(
        ln1, H_, (size_t)0, qkvw, H_, (size_t)0, qkv, QKV_OUT_, (size_t)0, H_, EpiStore{});
    // scores = Q K^T (causal tiles only, SIMT)
    k_scores<<<dim3(S_ / 64, S_ / 64, B_ * NH_), 256>>>(qkv, scores);
    // causal softmax
    k_softmax<<<dim3(S_, B_ * NH_), 256>>>(scores);
    // attn = P V (SIMT, causally clipped)
    k_pv<<<dim3(1, S_ / 64, B_ * NH_), 256>>>(scores, qkv, attn);
    // proj + residual (HMMA)
    k_hmma_nt<<<dim3(H_ / 128, T_ / 128, 1), 256, HMMA_SMEM_BYTES>>>(
        attn, H_, (size_t)0, projw, H_, (size_t)0, hattn, H_, (size_t)0, H_,
        EpiResidual{hidden, H_});
    // LN2
    k_layernorm<<<T_, 256>>>(hattn, ln2w, ln2b, ln2);
    // router top-2
    k_router<<<T_, 512>>>(ln2, routerw, expidx, gatep);
    // slot positions
    k_pos<<<1, 256>>>(expidx, pos);
    // zero + dispatch
    k_zero<<<(E_ * CAP_ * H_) / 4096, 1024>>>(buf);
    k_dispatch<<<NSLOT_, 256>>>(ln2, expidx, pos, buf);
    // expert FC1 (gelu) and FC2 (HMMA, batched over experts)
    k_hmma_nt<<<dim3(FFN_ / 128, CAP_ / 128, E_), 256, HMMA_SMEM_BYTES>>>(
        buf, H_, (size_t)CAP_ * H_, w1, H_, (size_t)FFN_ * H_,
        h1, FFN_, (size_t)CAP_ * FFN_, H_, EpiGelu{});
    k_hmma_nt<<<dim3(H_ / 128, CAP_ / 128, E_), 256, HMMA_SMEM_BYTES>>>(
        h1, FFN_, (size_t)CAP_ * FFN_, w2, FFN_, (size_t)H_ * FFN_,
        h2, H_, (size_t)CAP_ * H_, FFN_, EpiStore{});
    // combine + final residual
    k_combine<<<T_, 256>>>(hattn, h2, expidx, pos, gatep, out);
}

// round 4
// speedup vs baseline: 3.2545x; 1.5247x over previous
#include <cuda_runtime.h>
#include <cuda_bf16.h>
#include <math.h>
#include <stdint.h>

// ---------------- problem constants ----------------
#define S_   2048
#define B_   2
#define H_   1024
#define NH_  16
#define NKV_ 4
#define HD_  64
#define T_   4096            // S_*B_
#define QKV_OUT_ 1536
#define E_   16
#define TOPK_ 2
#define FFN_ 2048
#define CAP_ 640             // ceil(T*K/E*1.25)
#define NSLOT_ (T_*TOPK_)

// ---------------- scratch (device globals; no runtime allocation) ----------------
__device__ float g_ln1[(size_t)T_*H_];
__device__ float g_qkv[(size_t)T_*QKV_OUT_];
__device__ float g_attn[(size_t)T_*H_];
__device__ float g_hattn[(size_t)T_*H_];
__device__ float g_ln2[(size_t)T_*H_];
__device__ int   g_expidx[NSLOT_];
__device__ int   g_pos[NSLOT_];
__device__ float g_gate[NSLOT_];
__device__ float g_buf[(size_t)E_*CAP_*H_];
__device__ float g_h1[(size_t)E_*CAP_*FFN_];
__device__ float g_h2[(size_t)E_*CAP_*H_];

// =====================================================================
// PTX helpers (baseline sm_80+ ISA only — tcgen05 unavailable on this
// build target, verified by R2 ptxas errors)
// =====================================================================
__device__ __forceinline__ uint32_t smem_to_u32(const void* smem_ptr) {
    uint32_t addr;
    asm("{ .reg .u64 tmp; cvta.to.shared.u64 tmp, %1; cvt.u32.u64 %0, tmp; }"
        : "=r"(addr) : "l"(smem_ptr));
    return addr;
}

#define CVT_BF16X2_F32(result, a, b) \
    asm("cvt.rn.satfinite.bf16x2.f32 %0, %1, %2;" : "=r"(result) : "f"(b), "f"(a))

__device__ __forceinline__ void ldsm_x4(uint32_t& r0, uint32_t& r1,
                                        uint32_t& r2, uint32_t& r3, uint32_t addr) {
    asm volatile("ldmatrix.sync.aligned.m8n8.x4.shared.b16 {%0,%1,%2,%3}, [%4];"
                 : "=r"(r0), "=r"(r1), "=r"(r2), "=r"(r3) : "r"(addr));
}
__device__ __forceinline__ void ldsm_x4_t(uint32_t& r0, uint32_t& r1,
                                          uint32_t& r2, uint32_t& r3, uint32_t addr) {
    asm volatile("ldmatrix.sync.aligned.m8n8.x4.trans.shared.b16 {%0,%1,%2,%3}, [%4];"
                 : "=r"(r0), "=r"(r1), "=r"(r2), "=r"(r3) : "r"(addr));
}

__device__ __forceinline__ void mma16816(float* c,
        uint32_t a0, uint32_t a1, uint32_t a2, uint32_t a3,
        uint32_t b0, uint32_t b1) {
    asm volatile(
        "mma.sync.aligned.m16n8k16.row.col.f32.bf16.bf16.f32 "
        "{%0,%1,%2,%3}, {%4,%5,%6,%7}, {%8,%9}, {%0,%1,%2,%3};"
        : "+f"(c[0]), "+f"(c[1]), "+f"(c[2]), "+f"(c[3])
        : "r"(a0), "r"(a1), "r"(a2), "r"(a3), "r"(b0), "r"(b1));
}

// fp32 -> (hi, lo) bf16 split of a float4
__device__ __forceinline__ void cvt_split(float4 v, uint2& hi, uint2& lo) {
    uint32_t h01, h23, l01, l23;
    CVT_BF16X2_F32(h01, v.x, v.y);
    CVT_BF16X2_F32(h23, v.z, v.w);
    float f0 = __uint_as_float(h01 << 16), f1 = __uint_as_float(h01 & 0xFFFF0000u);
    float f2 = __uint_as_float(h23 << 16), f3 = __uint_as_float(h23 & 0xFFFF0000u);
    CVT_BF16X2_F32(l01, v.x - f0, v.y - f1);
    CVT_BF16X2_F32(l23, v.z - f2, v.w - f3);
    hi = make_uint2(h01, h23); lo = make_uint2(l01, l23);
}

// ---------------- epilogues ----------------
struct EpiStore {
    __device__ __forceinline__ float op(float v, int, int) const { return v; }
};
struct EpiResidual {
    const float* r; int ld;
    __device__ __forceinline__ float op(float v, int m, int n) const {
        return v + r[(size_t)m * ld + n];
    }
};
struct EpiGelu {
    __device__ __forceinline__ float op(float v, int, int) const {
        float c = 0.7978845608028654f;
        float t = tanhf(c * (v + 0.044715f * v * v * v));
        return 0.5f * v * (1.0f + t);
    }
};

// =====================================================================
// split-bf16 HMMA NT GEMM (unchanged from R3; 2657us baseline)
// =====================================================================
#define CH_  64
#define AST  136
#define HMMA_SMEM_BYTES (2 * 128 * AST * 2)   // 69632

template<typename Epi>
__global__ void __launch_bounds__(256, 2)
k_hmma_nt(const float* __restrict__ A, int lda, size_t aB,
          const float* __restrict__ B, int ldb, size_t bB,
          float* __restrict__ C, int ldc, size_t cB,
          int K, Epi epi)
{
    extern __shared__ __nv_bfloat16 sm[];
    __nv_bfloat16 (*As)[AST] = (__nv_bfloat16(*)[AST])sm;
    __nv_bfloat16 (*Bs)[AST] = (__nv_bfloat16(*)[AST])(sm + 128 * AST);

    const int tid = threadIdx.x, lane = tid & 31, wid = tid >> 5;
    const int m0 = blockIdx.y * 128, n0 = blockIdx.x * 128;
    A += (size_t)blockIdx.z * aB;
    B += (size_t)blockIdx.z * bB;
    C += (size_t)blockIdx.z * cB;
    const int warpM = (wid >> 2) * 64, warpN = (wid & 3) * 32;

    float acc[4][4][4] = {};

    const uint32_t sA = smem_to_u32(As), sB = smem_to_u32(Bs);
    const int lrow = lane & 15, lsel = lane >> 4;

    for (int k0 = 0; k0 < K; k0 += CH_) {
        #pragma unroll
        for (int i = 0; i < 8; i++) {
            int f = tid + i * 256;
            int row = f >> 4, kq = f & 15;

            float4 va = *(const float4*)&A[(size_t)(m0 + row) * lda + k0 + kq * 4];
            uint2 hi, lo;
            cvt_split(va, hi, lo);
            *(uint2*)&As[row][kq * 4]      = hi;
            *(uint2*)&As[row][64 + kq * 4] = lo;

            float4 vb = *(const float4*)&B[(size_t)(n0 + row) * ldb + k0 + kq * 4];
            cvt_split(vb, hi, lo);
            *(uint2*)&Bs[row][kq * 4]      = hi;
            *(uint2*)&Bs[row][64 + kq * 4] = lo;
        }
        __syncthreads();

        const int AO[12] = {0,16,32,48, 64,80,96,112, 0,16,32,48};
        const int BO[12] = {0,16,32,48, 0,16,32,48, 64,80,96,112};
        #pragma unroll
        for (int s = 0; s < 12; s++) {
            uint32_t af[4][4];
            #pragma unroll
            for (int mt = 0; mt < 4; mt++) {
                uint32_t addr = sA +
                    ((uint32_t)(warpM + mt * 16 + lrow) * AST + AO[s] + lsel * 8) * 2;
                ldsm_x4(af[mt][0], af[mt][1], af[mt][2], af[mt][3], addr);
            }
            uint32_t bf[4][2];
            #pragma unroll
            for (int pt = 0; pt < 2; pt++) {
                uint32_t r0, r1, r2, r3;
                uint32_t addr = sB +
                    ((uint32_t)(warpN + pt * 16 + lrow) * AST + BO[s] + lsel * 8) * 2;
                ldsm_x4(r0, r1, r2, r3, addr);
                bf[pt * 2][0] = r0;     bf[pt * 2][1] = r2;
                bf[pt * 2 + 1][0] = r1; bf[pt * 2 + 1][1] = r3;
            }
            #pragma unroll
            for (int mt = 0; mt < 4; mt++)
                #pragma unroll
                for (int nt = 0; nt < 4; nt++)
                    mma16816(acc[mt][nt], af[mt][0], af[mt][1], af[mt][2], af[mt][3],
                             bf[nt][0], bf[nt][1]);
        }
        __syncthreads();
    }

    const int r = lane >> 2, cpair = (lane & 3) * 2;
    #pragma unroll
    for (int mt = 0; mt < 4; mt++) {
        int gm0 = m0 + warpM + mt * 16 + r;
        #pragma unroll
        for (int nt = 0; nt < 4; nt++) {
            int gn = n0 + warpN + nt * 8 + cpair;
            float2 v0 = make_float2(epi.op(acc[mt][nt][0], gm0, gn),
                                    epi.op(acc[mt][nt][1], gm0, gn + 1));
            *(float2*)&C[(size_t)gm0 * ldc + gn] = v0;
            float2 v1 = make_float2(epi.op(acc[mt][nt][2], gm0 + 8, gn),
                                    epi.op(acc[mt][nt][3], gm0 + 8, gn + 1));
            *(float2*)&C[(size_t)(gm0 + 8) * ldc + gn] = v1;
        }
    }
}

// =====================================================================
// Fused flash attention, split-bf16 HMMA, causal GQA.
// Grid: (B*NH, S/128). Block: 256 threads = 8 warps, each warp 16 q-rows.
// Q tile 128x64 resident in SMEM (split bf16). K/V tiles 64x64 per iter.
// S = Q K^T via 3-product split HMMA; online softmax in accumulator
// registers; P re-split to bf16 A-fragments in registers; O += P V via
// 3-product split HMMA with ldmatrix.trans B-fragments of V.
// =====================================================================
#define FL_QROWS 128
#define FL_KT    64
#define FL_AST   136            // bf16 row stride: [hi 64 | lo 64 | pad 8]
#define FL_RB    (FL_AST * 2)   // 272 bytes per row
#define FLASH_SMEM ((FL_QROWS + 2 * FL_KT) * FL_RB)   // 69632

__global__ void __launch_bounds__(256)
k_flash(const float* __restrict__ qkv, float* __restrict__ attn)
{
    extern __shared__ char sm8[];
    const uint32_t sQ = smem_to_u32(sm8);
    const uint32_t sK = sQ + FL_QROWS * FL_RB;
    const uint32_t sV = sK + FL_KT * FL_RB;
    char* pQ = sm8;
    char* pK = sm8 + FL_QROWS * FL_RB;
    char* pV = pK + FL_KT * FL_RB;

    const int tid = threadIdx.x, lane = tid & 31, wid = tid >> 5;
    const int lrow = lane & 15, lsel = lane >> 4;
    const int bh = blockIdx.x;
    const int b = bh >> 4, hq = bh & 15, hk = hq >> 2;
    const int q0 = (int)(gridDim.y - 1 - blockIdx.y) * FL_QROWS;  // big tiles first

    const int seqstride = B_ * QKV_OUT_;
    const float* Qg = qkv + (size_t)b * QKV_OUT_ + hq * HD_;
    const float* Kg = qkv + (size_t)b * QKV_OUT_ + NH_ * HD_ + hk * HD_;
    const float* Vg = qkv + (size_t)b * QKV_OUT_ + (NH_ + NKV_) * HD_ + hk * HD_;

    // ---- load Q tile once (split bf16) ----
    #pragma unroll
    for (int i = 0; i < 8; i++) {
        int f = tid + i * 256;
        int row = f >> 4, c4 = f & 15;
        float4 v = *(const float4*)&Qg[(size_t)(q0 + row) * seqstride + c4 * 4];
        uint2 hi, lo;
        cvt_split(v, hi, lo);
        char* pr = pQ + row * FL_RB;
        *(uint2*)(pr + c4 * 8) = hi;
        *(uint2*)(pr + 128 + c4 * 8) = lo;
    }

    float accO[8][4] = {};
    float S[8][4];
    float m0 = -1e30f, m1 = -1e30f, l0 = 0.f, l1 = 0.f;

    const int rbase = q0 + wid * 16;          // warp's first q row
    const int q_hi = rbase + 15;              // warp's last q row
    const int jmax = (q0 >> 6) + 2;           // causal tile bound for block

    for (int j = 0; j < jmax; j++) {
        const int jbase = j * FL_KT;
        // ---- load K/V tiles (split bf16) ----
        #pragma unroll
        for (int i = 0; i < 4; i++) {
            int f = tid + i * 256;
            int row = f >> 4, c4 = f & 15;
            size_t go = (size_t)(jbase + row) * seqstride + c4 * 4;
            uint2 hi, lo;
            float4 v = *(const float4*)&Kg[go];
            cvt_split(v, hi, lo);
            char* pr = pK + row * FL_RB;
            *(uint2*)(pr + c4 * 8) = hi;
            *(uint2*)(pr + 128 + c4 * 8) = lo;
            v = *(const float4*)&Vg[go];
            cvt_split(v, hi, lo);
            pr = pV + row * FL_RB;
            *(uint2*)(pr + c4 * 8) = hi;
            *(uint2*)(pr + 128 + c4 * 8) = lo;
        }
        __syncthreads();

        if (jbase <= q_hi) {
            // ================= S = Q K^T (split, 3 products) ================
            #pragma unroll
            for (int t = 0; t < 8; t++) {
                S[t][0] = 0.f; S[t][1] = 0.f; S[t][2] = 0.f; S[t][3] = 0.f;
            }
            #pragma unroll
            for (int s = 0; s < 4; s++) {
                uint32_t qh[4], ql[4], kb[4][2];
                uint32_t qaddr = sQ + (uint32_t)(wid * 16 + lrow) * FL_RB +
                                 (s * 16 + lsel * 8) * 2;
                ldsm_x4(qh[0], qh[1], qh[2], qh[3], qaddr);
                ldsm_x4(ql[0], ql[1], ql[2], ql[3], qaddr + 128);
                // K hi fragments for all 8 key n-tiles
                #pragma unroll
                for (int g = 0; g < 4; g++) {
                    uint32_t r0, r1, r2, r3;
                    uint32_t kaddr = sK + (uint32_t)(g * 16 + lrow) * FL_RB +
                                     (s * 16 + lsel * 8) * 2;
                    ldsm_x4(r0, r1, r2, r3, kaddr);
                    kb[g][0] = r0; kb[g][1] = r2;
                    // immediately consume second tile regs via locals
                    mma16816(S[g * 2 + 1], qh[0], qh[1], qh[2], qh[3], r1, r3);
                    mma16816(S[g * 2 + 1], ql[0], ql[1], ql[2], ql[3], r1, r3);
                }
                #pragma unroll
                for (int g = 0; g < 4; g++) {
                    mma16816(S[g * 2], qh[0], qh[1], qh[2], qh[3], kb[g][0], kb[g][1]);
                    mma16816(S[g * 2], ql[0], ql[1], ql[2], ql[3], kb[g][0], kb[g][1]);
                }
                // K lo fragments (with Q hi)
                #pragma unroll
                for (int g = 0; g < 4; g++) {
                    uint32_t r0, r1, r2, r3;
                    uint32_t kaddr = sK + (uint32_t)(g * 16 + lrow) * FL_RB +
                                     (64 + s * 16 + lsel * 8) * 2;
                    ldsm_x4(r0, r1, r2, r3, kaddr);
                    mma16816(S[g * 2],     qh[0], qh[1], qh[2], qh[3], r0, r2);
                    mma16816(S[g * 2 + 1], qh[0], qh[1], qh[2], qh[3], r1, r3);
                }
            }

            // ================= scale + causal mask ================
            const float scale = 0.125f;
            #pragma unroll
            for (int t = 0; t < 8; t++) {
                S[t][0] *= scale; S[t][1] *= scale;
                S[t][2] *= scale; S[t][3] *= scale;
            }
            if (jbase + 63 > rbase) {
                int r0g = rbase + (lane >> 2);
                int cg = jbase + (lane & 3) * 2;
                #pragma unroll
                for (int t = 0; t < 8; t++) {
                    int c0 = cg + t * 8;
                    if (c0 > r0g)     S[t][0] = -1e30f;
                    if (c0 + 1 > r0g) S[t][1] = -1e30f;
                    if (c0 > r0g + 8)     S[t][2] = -1e30f;
                    if (c0 + 1 > r0g + 8) S[t][3] = -1e30f;
                }
            }

            // ================= online softmax ================
            float tm0 = -1e30f, tm1 = -1e30f;
            #pragma unroll
            for (int t = 0; t < 8; t++) {
                tm0 = fmaxf(tm0, fmaxf(S[t][0], S[t][1]));
                tm1 = fmaxf(tm1, fmaxf(S[t][2], S[t][3]));
            }
            tm0 = fmaxf(tm0, __shfl_xor_sync(0xFFFFFFFFu, tm0, 1));
            tm0 = fmaxf(tm0, __shfl_xor_sync(0xFFFFFFFFu, tm0, 2));
            tm1 = fmaxf(tm1, __shfl_xor_sync(0xFFFFFFFFu, tm1, 1));
            tm1 = fmaxf(tm1, __shfl_xor_sync(0xFFFFFFFFu, tm1, 2));
            float mn0 = fmaxf(m0, tm0), mn1 = fmaxf(m1, tm1);
            float fac0 = __expf(m0 - mn0), fac1 = __expf(m1 - mn1);

            float ts0 = 0.f, ts1 = 0.f;
            #pragma unroll
            for (int t = 0; t < 8; t++) {
                S[t][0] = __expf(S[t][0] - mn0);
                S[t][1] = __expf(S[t][1] - mn0);
                S[t][2] = __expf(S[t][2] - mn1);
                S[t][3] = __expf(S[t][3] - mn1);
                ts0 += S[t][0] + S[t][1];
                ts1 += S[t][2] + S[t][3];
            }
            ts0 += __shfl_xor_sync(0xFFFFFFFFu, ts0, 1);
            ts0 += __shfl_xor_sync(0xFFFFFFFFu, ts0, 2);
            ts1 += __shfl_xor_sync(0xFFFFFFFFu, ts1, 1);
            ts1 += __shfl_xor_sync(0xFFFFFFFFu, ts1, 2);
            l0 = l0 * fac0 + ts0;
            l1 = l1 * fac1 + ts1;
            m0 = mn0; m1 = mn1;

            #pragma unroll
            for (int t = 0; t < 8; t++) {
                accO[t][0] *= fac0; accO[t][1] *= fac0;
                accO[t][2] *= fac1; accO[t][3] *= fac1;
            }

            // ================= O += P V (split, 3 products) ================
            #pragma unroll
            for (int s = 0; s < 4; s++) {
                // P fragments from S accumulators (registers only)
                uint32_t ah[4], al[4];
                CVT_BF16X2_F32(ah[0], S[2*s][0],   S[2*s][1]);
                CVT_BF16X2_F32(ah[1], S[2*s][2],   S[2*s][3]);
                CVT_BF16X2_F32(ah[2], S[2*s+1][0], S[2*s+1][1]);
                CVT_BF16X2_F32(ah[3], S[2*s+1][2], S[2*s+1][3]);
                #pragma unroll
                for (int i = 0; i < 4; i++) {
                    const float* sp = (i < 2) ? S[2*s] : S[2*s+1];
                    int o = (i & 1) * 2;
                    float flo = __uint_as_float(ah[i] << 16);
                    float fhi = __uint_as_float(ah[i] & 0xFFFF0000u);
                    CVT_BF16X2_F32(al[i], sp[o] - flo, sp[o + 1] - fhi);
                }
                #pragma unroll
                for (int dg = 0; dg < 4; dg++) {
                    uint32_t vrow = (uint32_t)(s * 16 + ((lane >> 3) & 1) * 8 + (lane & 7));
                    uint32_t vcol = (uint32_t)(dg * 16 + (lane >> 4) * 8);
                    uint32_t vaddr = sV + vrow * FL_RB + vcol * 2;
                    uint32_t h0, h1, h2, h3;
                    ldsm_x4_t(h0, h1, h2, h3, vaddr);
                    mma16816(accO[dg * 2],     ah[0], ah[1], ah[2], ah[3], h0, h1);
                    mma16816(accO[dg * 2],     al[0], al[1], al[2], al[3], h0, h1);
                    mma16816(accO[dg * 2 + 1], ah[0], ah[1], ah[2], ah[3], h2, h3);
                    mma16816(accO[dg * 2 + 1], al[0], al[1], al[2], al[3], h2, h3);
                    uint32_t g0, g1, g2, g3;
                    ldsm_x4_t(g0, g1, g2, g3, vaddr + 128);
                    mma16816(accO[dg * 2],     ah[0], ah[1], ah[2], ah[3], g0, g1);
                    mma16816(accO[dg * 2 + 1], ah[0], ah[1], ah[2], ah[3], g2, g3);
                }
            }
        }
        __syncthreads();
    }

    // ---- finalize: O /= l, write [S,B,H] ----
    float inv0 = 1.f / l0, inv1 = 1.f / l1;
    int r0g = rbase + (lane >> 2);
    float* Og = attn + (size_t)b * H_ + hq * HD_;
    const int ostride = B_ * H_;
    #pragma unroll
    for (int t = 0; t < 8; t++) {
        int gd = t * 8 + (lane & 3) * 2;
        *(float2*)&Og[(size_t)r0g * ostride + gd] =
            make_float2(accO[t][0] * inv0, accO[t][1] * inv0);
        *(float2*)&Og[(size_t)(r0g + 8) * ostride + gd] =
            make_float2(accO[t][2] * inv1, accO[t][3] * inv1);
    }
}

// ---------------- layernorm ----------------
__global__ void k_layernorm(const float* __restrict__ x, const float* __restrict__ w,
                            const float* __restrict__ b, float* __restrict__ y)
{
    int t = blockIdx.x;
    const float* xr = x + (size_t)t * H_;
    float* yr = y + (size_t)t * H_;
    float v[4], s = 0.f, s2 = 0.f;
    #pragma unroll
    for (int i = 0; i < 4; i++) {
        v[i] = xr[threadIdx.x + i * 256];
        s += v[i]; s2 += v[i] * v[i];
    }
    __shared__ float r1[256], r2[256];
    r1[threadIdx.x] = s; r2[threadIdx.x] = s2;
    __syncthreads();
    for (int o = 128; o; o >>= 1) {
        if (threadIdx.x < o) {
            r1[threadIdx.x] += r1[threadIdx.x + o];
            r2[threadIdx.x] += r2[threadIdx.x + o];
        }
        __syncthreads();
    }
    float mean = r1[0] * (1.0f / H_);
    float var  = r2[0] * (1.0f / H_) - mean * mean;
    float inv  = rsqrtf(var + 1e-5f);
    #pragma unroll
    for (int i = 0; i < 4; i++) {
        int h = threadIdx.x + i * 256;
        yr[h] = (v[i] - mean) * inv * w[h] + b[h];
    }
}

// ---------------- router ----------------
__global__ void k_router(const float* __restrict__ ln2, const float* __restrict__ Wr,
                         int* __restrict__ expidx, float* __restrict__ gate)
{
    int t = blockIdx.x;
    __shared__ float logits[E_];
    int w = threadIdx.x >> 5, lane = threadIdx.x & 31;
    const float* x = ln2 + (size_t)t * H_;
    const float* wr = Wr + (size_t)w * H_;
    float s = 0.f;
    for (int i = lane; i < H_; i += 32) s += x[i] * wr[i];
    #pragma unroll
    for (int o = 16; o; o >>= 1) s += __shfl_xor_sync(0xFFFFFFFFu, s, o);
    if (lane == 0) logits[w] = s;
    __syncthreads();
    if (threadIdx.x == 0) {
        float lmax = -1e30f;
        #pragma unroll
        for (int e = 0; e < E_; e++) lmax = fmaxf(lmax, logits[e]);
        float den = 0.f;
        #pragma unroll
        for (int e = 0; e < E_; e++) den += expf(logits[e] - lmax);
        int i1 = 0; float v1 = logits[0];
        #pragma unroll
        for (int e = 1; e < E_; e++) if (logits[e] > v1) { v1 = logits[e]; i1 = e; }
        int i2 = -1; float v2 = -1e30f;
        #pragma unroll
        for (int e = 0; e < E_; e++) if (e != i1 && logits[e] > v2) { v2 = logits[e]; i2 = e; }
        float inv = 1.0f / den;
        expidx[2 * t]     = i1;  gate[2 * t]     = expf(v1 - lmax) * inv;
        expidx[2 * t + 1] = i2;  gate[2 * t + 1] = expf(v2 - lmax) * inv;
    }
}

// ---------------- slot positions ----------------
__global__ void k_pos(const int* __restrict__ expidx, int* __restrict__ pos)
{
    __shared__ int sidx[NSLOT_];
    for (int i = threadIdx.x; i < NSLOT_; i += blockDim.x) sidx[i] = expidx[i];
    __syncthreads();
    if (threadIdx.x < E_) {
        int e = threadIdx.x, c = 0;
        for (int j = 0; j < NSLOT_; j++)
            if (sidx[j] == e) pos[j] = c++;
    }
}

__global__ void k_zero(float* __restrict__ p)
{
    float4 z = make_float4(0.f, 0.f, 0.f, 0.f);
    ((float4*)p)[(size_t)blockIdx.x * 1024 + threadIdx.x] = z;
}

__global__ void k_dispatch(const float* __restrict__ ln2, const int* __restrict__ expidx,
                           const int* __restrict__ pos, float* __restrict__ buf)
{
    int slot = blockIdx.x;
    int p = pos[slot];
    if (p >= CAP_) return;
    int e = expidx[slot];
    int t = slot >> 1;
    const float* src = ln2 + (size_t)t * H_;
    float* dst = buf + ((size_t)e * CAP_ + p) * H_;
    for (int h = threadIdx.x; h < H_; h += 256) dst[h] = src[h];
}

__global__ void k_combine(const float* __restrict__ hattn, const float* __restrict__ h2,
                          const int* __restrict__ expidx, const int* __restrict__ pos,
                          const float* __restrict__ gate, float* __restrict__ out)
{
    int t = blockIdx.x;
    int s0 = 2 * t, s1 = 2 * t + 1;
    int p0 = pos[s0], p1 = pos[s1];
    int e0 = expidx[s0], e1 = expidx[s1];
    float g0 = (p0 < CAP_) ? gate[s0] : 0.f;
    float g1 = (p1 < CAP_) ? gate[s1] : 0.f;
    const float* r0 = (p0 < CAP_) ? h2 + ((size_t)e0 * CAP_ + p0) * H_ : nullptr;
    const float* r1 = (p1 < CAP_) ? h2 + ((size_t)e1 * CAP_ + p1) * H_ : nullptr;
    for (int h = threadIdx.x; h < H_; h += 256) {
        float v = hattn[(size_t)t * H_ + h];
        if (r0) v += r0[h] * g0;
        if (r1) v += r1[h] * g1;
        out[(size_t)t * H_ + h] = v;
    }
}

// ---------------- launch ----------------
extern "C" void kernel_launch(void* const* d_in, const int* in_sizes, int n_in,
                              void* d_out, int out_size)
{
    const float* hidden  = (const float*)d_in[0];
    const float* ln1w    = (const float*)d_in[1];
    const float* ln1b    = (const float*)d_in[2];
    const float* ln2w    = (const float*)d_in[3];
    const float* ln2b    = (const float*)d_in[4];
    const float* qkvw    = (const float*)d_in[5];
    const float* projw   = (const float*)d_in[6];
    const float* routerw = (const float*)d_in[7];
    const float* w1      = (const float*)d_in[8];
    const float* w2      = (const float*)d_in[9];
    float* out = (float*)d_out;

    float *ln1, *qkv, *attn, *hattn, *ln2, *gatep, *buf, *h1, *h2;
    int *expidx, *pos;
    cudaGetSymbolAddress((void**)&ln1,    g_ln1);
    cudaGetSymbolAddress((void**)&qkv,    g_qkv);
    cudaGetSymbolAddress((void**)&attn,   g_attn);
    cudaGetSymbolAddress((void**)&hattn,  g_hattn);
    cudaGetSymbolAddress((void**)&ln2,    g_ln2);
    cudaGetSymbolAddress((void**)&expidx, g_expidx);
    cudaGetSymbolAddress((void**)&pos,    g_pos);
    cudaGetSymbolAddress((void**)&gatep,  g_gate);
    cudaGetSymbolAddress((void**)&buf,    g_buf);
    cudaGetSymbolAddress((void**)&h1,     g_h1);
    cudaGetSymbolAddress((void**)&h2,     g_h2);

    cudaFuncSetAttribute((void*)k_hmma_nt<EpiStore>,
                         cudaFuncAttributeMaxDynamicSharedMemorySize, HMMA_SMEM_BYTES);
    cudaFuncSetAttribute((void*)k_hmma_nt<EpiResidual>,
                         cudaFuncAttributeMaxDynamicSharedMemorySize, HMMA_SMEM_BYTES);
    cudaFuncSetAttribute((void*)k_hmma_nt<EpiGelu>,
                         cudaFuncAttributeMaxDynamicSharedMemorySize, HMMA_SMEM_BYTES);
    cudaFuncSetAttribute((void*)k_flash,
                         cudaFuncAttributeMaxDynamicSharedMemorySize, FLASH_SMEM);

    // LN1
    k_layernorm<<<T_, 256>>>(hidden, ln1w, ln1b, ln1);
    // QKV = ln1 @ W_qkv^T (HMMA split-bf16)
    k_hmma_nt<<<dim3(QKV_OUT_ / 128, T_ / 128, 1), 256, HMMA_SMEM_BYTES>>>(
        ln1, H_, (size_t)0, qkvw, H_, (size_t)0, qkv, QKV_OUT_, (size_t)0, H_, EpiStore{});
    // fused causal flash attention (HMMA split-bf16)
    k_flash<<<dim3(B_ * NH_, S_ / FL_QROWS), 256, FLASH_SMEM>>>(qkv, attn);
    // proj + residual (HMMA)
    k_hmma_nt<<<dim3(H_ / 128, T_ / 128, 1), 256, HMMA_SMEM_BYTES>>>(
        attn, H_, (size_t)0, projw, H_, (size_t)0, hattn, H_, (size_t)0, H_,
        EpiResidual{hidden, H_});
    // LN2
    k_layernorm<<<T_, 256>>>(hattn, ln2w, ln2b, ln2);
    // router top-2
    k_router<<<T_, 512>>>(ln2, routerw, expidx, gatep);
    // slot positions
    k_pos<<<1, 256>>>(expidx, pos);
    // zero + dispatch
    k_zero<<<(E_ * CAP_ * H_) / 4096, 1024>>>(buf);
    k_dispatch<<<NSLOT_, 256>>>(ln2, expidx, pos, buf);
    // expert FC1 (gelu) and FC2 (HMMA, batched over experts)
    k_hmma_nt<<<dim3(FFN_ / 128, CAP_ / 128, E_), 256, HMMA_SMEM_BYTES>>>(
        buf, H_, (size_t)CAP_ * H_, w1, H_, (size_t)FFN_ * H_,
        h1, FFN_, (size_t)CAP_ * FFN_, H_, EpiGelu{});
    k_hmma_nt<<<dim3(H_ / 128, CAP_ / 128, E_), 256, HMMA_SMEM_BYTES>>>(
        h1, FFN_, (size_t)CAP_ * FFN_, w2, FFN_, (size_t)H_ * FFN_,
        h2, H_, (size_t)CAP_ * H_, FFN_, EpiStore{});
    // combine + final residual
    k_combine<<<T_, 256>>>(hattn, h2, expidx, pos, gatep, out);
}